// round 6
// baseline (speedup 1.0000x reference)
#include <cuda_runtime.h>
#include <cuda_bf16.h>

// ExpmLogm on symmetric 3x3 per-voxel matrices collapses to the identity:
//   eigh(M) -> (S,U); log(exp(S)) = S; U diag(S) U^T = M  (== input).
// Optimal = streaming D2D copy of ~302 MB.
//
// Measured across rounds: SM copy kernel ~41.3us @ ~7.3 TB/s (91% of HBM
// spec), driver memcpy node equivalent. Saturated roofline; this is the
// best-measured variant (ILP=4, streaming hints) with an exact-division
// fast path that drops all bounds predicates (grid covers n4 exactly).

#define VPT 4          // float4 per thread
#define TPB 256        // threads per block

// Exact-fit path: grid*TPB*VPT == n4, no predicates.
__global__ __launch_bounds__(TPB) void expmlogm_copy_exact(
    const float4* __restrict__ in, float4* __restrict__ out) {
    int base = blockIdx.x * (TPB * VPT) + threadIdx.x;
    float4 v[VPT];
    #pragma unroll
    for (int k = 0; k < VPT; k++) v[k] = __ldcs(&in[base + k * TPB]);
    #pragma unroll
    for (int k = 0; k < VPT; k++) __stcs(&out[base + k * TPB], v[k]);
}

// Generic predicated path (fallback for non-divisible sizes).
__global__ __launch_bounds__(TPB) void expmlogm_copy_kernel(
    const float4* __restrict__ in, float4* __restrict__ out, int n4) {
    int base = blockIdx.x * (TPB * VPT) + threadIdx.x;
    float4 v[VPT];
    int idx[VPT];
    #pragma unroll
    for (int k = 0; k < VPT; k++) {
        idx[k] = base + k * TPB;
        if (idx[k] < n4) v[k] = __ldcs(&in[idx[k]]);
    }
    #pragma unroll
    for (int k = 0; k < VPT; k++) {
        if (idx[k] < n4) __stcs(&out[idx[k]], v[k]);
    }
}

__global__ void expmlogm_copy_tail(const float* __restrict__ in,
                                   float* __restrict__ out,
                                   int start, int n) {
    int i = start + blockIdx.x * blockDim.x + threadIdx.x;
    if (i < n) out[i] = in[i];
}

extern "C" void kernel_launch(void* const* d_in, const int* in_sizes, int n_in,
                              void* d_out, int out_size) {
    const float* x = (const float*)d_in[0];
    float* out = (float*)d_out;
    int n = in_sizes[0];

    int n4 = n / 4;
    int per_block = TPB * VPT;

    if (n4 > 0 && n4 % per_block == 0) {
        // Hot path for this problem: n4 = 9,437,184 = 9216 * 1024.
        expmlogm_copy_exact<<<n4 / per_block, TPB>>>(
            (const float4*)x, (float4*)out);
    } else if (n4 > 0) {
        int blocks = (n4 + per_block - 1) / per_block;
        expmlogm_copy_kernel<<<blocks, TPB>>>(
            (const float4*)x, (float4*)out, n4);
    }
    int tail_start = n4 * 4;
    if (n - tail_start > 0) {
        expmlogm_copy_tail<<<1, 128>>>(x, out, tail_start, n);
    }
}

// round 7
// speedup vs baseline: 1.0390x; 1.0390x over previous
#include <cuda_runtime.h>
#include <cuda_bf16.h>

// ExpmLogm on symmetric 3x3 per-voxel matrices collapses to the identity:
//   eigh(M) -> (S,U); log(exp(S)) = S; U diag(S) U^T = M  (== input).
// Optimal = streaming D2D copy of ~302 MB.
//
// Saturated HBM roofline: exact-fit kernel measured 39.9us (~7.57 TB/s wall,
// ~95% of 8 TB/s spec; physical floor 37.7us). dur_us variance across rounds
// is harness replay overhead (~8-11us), not kernel time. This round re-benches
// the best-measured kernel unchanged to sample that noise.

#define VPT 4          // float4 per thread
#define TPB 256        // threads per block

// Exact-fit path: grid*TPB*VPT == n4, no predicates, front-batched loads.
__global__ __launch_bounds__(TPB) void expmlogm_copy_exact(
    const float4* __restrict__ in, float4* __restrict__ out) {
    int base = blockIdx.x * (TPB * VPT) + threadIdx.x;
    float4 v[VPT];
    #pragma unroll
    for (int k = 0; k < VPT; k++) v[k] = __ldcs(&in[base + k * TPB]);
    #pragma unroll
    for (int k = 0; k < VPT; k++) __stcs(&out[base + k * TPB], v[k]);
}

// Generic predicated path (fallback for non-divisible sizes; unused here).
__global__ __launch_bounds__(TPB) void expmlogm_copy_kernel(
    const float4* __restrict__ in, float4* __restrict__ out, int n4) {
    int base = blockIdx.x * (TPB * VPT) + threadIdx.x;
    float4 v[VPT];
    int idx[VPT];
    #pragma unroll
    for (int k = 0; k < VPT; k++) {
        idx[k] = base + k * TPB;
        if (idx[k] < n4) v[k] = __ldcs(&in[idx[k]]);
    }
    #pragma unroll
    for (int k = 0; k < VPT; k++) {
        if (idx[k] < n4) __stcs(&out[idx[k]], v[k]);
    }
}

__global__ void expmlogm_copy_tail(const float* __restrict__ in,
                                   float* __restrict__ out,
                                   int start, int n) {
    int i = start + blockIdx.x * blockDim.x + threadIdx.x;
    if (i < n) out[i] = in[i];
}

extern "C" void kernel_launch(void* const* d_in, const int* in_sizes, int n_in,
                              void* d_out, int out_size) {
    const float* x = (const float*)d_in[0];
    float* out = (float*)d_out;
    int n = in_sizes[0];

    int n4 = n / 4;
    int per_block = TPB * VPT;

    if (n4 > 0 && n4 % per_block == 0) {
        // Hot path for this problem: n4 = 9,437,184 = 9216 * 1024.
        expmlogm_copy_exact<<<n4 / per_block, TPB>>>(
            (const float4*)x, (float4*)out);
    } else if (n4 > 0) {
        int blocks = (n4 + per_block - 1) / per_block;
        expmlogm_copy_kernel<<<blocks, TPB>>>(
            (const float4*)x, (float4*)out, n4);
    }
    int tail_start = n4 * 4;
    if (n - tail_start > 0) {
        expmlogm_copy_tail<<<1, 128>>>(x, out, tail_start, n);
    }
}

// round 9
// speedup vs baseline: 1.0492x; 1.0098x over previous
#include <cuda_runtime.h>
#include <cuda_bf16.h>

// ExpmLogm on symmetric 3x3 per-voxel matrices collapses to the identity:
//   eigh(M) -> (S,U); log(exp(S)) = S; U diag(S) U^T = M  (== input).
// Optimal = streaming D2D copy of ~302 MB (irreducible read+write).
//
// Roofline status: exact-fit VPT=4 kernel measures 39.9-40.9us across runs
// (~7.4-7.6 TB/s wall, physical floor 37.7us @ 8 TB/s spec). This round A/Bs
// VPT=8 (deeper front-batched MLP, half the CTAs) as the final parameter.

#define VPT 8          // float4 per thread
#define TPB 256        // threads per block

// Exact-fit path: grid*TPB*VPT == n4, no predicates, front-batched loads.
__global__ __launch_bounds__(TPB) void expmlogm_copy_exact(
    const float4* __restrict__ in, float4* __restrict__ out) {
    int base = blockIdx.x * (TPB * VPT) + threadIdx.x;
    float4 v[VPT];
    #pragma unroll
    for (int k = 0; k < VPT; k++) v[k] = __ldcs(&in[base + k * TPB]);
    #pragma unroll
    for (int k = 0; k < VPT; k++) __stcs(&out[base + k * TPB], v[k]);
}

// Generic predicated path (fallback for non-divisible sizes; unused here).
__global__ __launch_bounds__(TPB) void expmlogm_copy_kernel(
    const float4* __restrict__ in, float4* __restrict__ out, int n4) {
    int base = blockIdx.x * (TPB * VPT) + threadIdx.x;
    float4 v[VPT];
    int idx[VPT];
    #pragma unroll
    for (int k = 0; k < VPT; k++) {
        idx[k] = base + k * TPB;
        if (idx[k] < n4) v[k] = __ldcs(&in[idx[k]]);
    }
    #pragma unroll
    for (int k = 0; k < VPT; k++) {
        if (idx[k] < n4) __stcs(&out[idx[k]], v[k]);
    }
}

__global__ void expmlogm_copy_tail(const float* __restrict__ in,
                                   float* __restrict__ out,
                                   int start, int n) {
    int i = start + blockIdx.x * blockDim.x + threadIdx.x;
    if (i < n) out[i] = in[i];
}

extern "C" void kernel_launch(void* const* d_in, const int* in_sizes, int n_in,
                              void* d_out, int out_size) {
    const float* x = (const float*)d_in[0];
    float* out = (float*)d_out;
    int n = in_sizes[0];

    int n4 = n / 4;
    int per_block = TPB * VPT;

    if (n4 > 0 && n4 % per_block == 0) {
        // Hot path for this problem: n4 = 9,437,184 = 4608 * 2048.
        expmlogm_copy_exact<<<n4 / per_block, TPB>>>(
            (const float4*)x, (float4*)out);
    } else if (n4 > 0) {
        int blocks = (n4 + per_block - 1) / per_block;
        expmlogm_copy_kernel<<<blocks, TPB>>>(
            (const float4*)x, (float4*)out, n4);
    }
    int tail_start = n4 * 4;
    if (n - tail_start > 0) {
        expmlogm_copy_tail<<<1, 128>>>(x, out, tail_start, n);
    }
}